// round 13
// baseline (speedup 1.0000x reference)
#include <cuda_runtime.h>

#define B_CONST 8192
#define D_CONST 4096
#define MARGIN 0.5f
#define THREADS 256

// Per-row hinge loss, overwritten every replay (no zeroing needed).
__device__ float g_loss[B_CONST];
// Completion counter; returns to 0 at the end of every launch (last block resets).
__device__ unsigned int g_count = 0;

__global__ __launch_bounds__(THREADS) void triplet_loss_kernel(
    const float* __restrict__ feats,
    const float* __restrict__ label,
    const int* __restrict__ idx1,
    const int* __restrict__ idx2,
    float* __restrict__ out)
{
    const int b = blockIdx.x;
    const int tid = threadIdx.x;

    const int i1 = idx1[b];
    const int i2 = idx2[b];

    const float4* __restrict__ a  = (const float4*)(feats + (long long)b  * D_CONST);
    const float4* __restrict__ t1 = (const float4*)(feats + (long long)i1 * D_CONST);
    const float4* __restrict__ t2 = (const float4*)(feats + (long long)i2 * D_CONST);

    float s_abs1 = 0.f, s_abs2 = 0.f, s_sq1 = 0.f, s_sq2 = 0.f;

    const int NV = D_CONST / 4;  // 1024 float4s per row
    #pragma unroll
    for (int i = tid; i < NV; i += THREADS) {
        float4 av = __ldg(a + i);
        float4 v1 = __ldg(t1 + i);
        float4 v2 = __ldg(t2 + i);

        float d;
        d = av.x - v1.x; s_abs1 += fabsf(d); s_sq1 = fmaf(d, d, s_sq1);
        d = av.y - v1.y; s_abs1 += fabsf(d); s_sq1 = fmaf(d, d, s_sq1);
        d = av.z - v1.z; s_abs1 += fabsf(d); s_sq1 = fmaf(d, d, s_sq1);
        d = av.w - v1.w; s_abs1 += fabsf(d); s_sq1 = fmaf(d, d, s_sq1);

        d = av.x - v2.x; s_abs2 += fabsf(d); s_sq2 = fmaf(d, d, s_sq2);
        d = av.y - v2.y; s_abs2 += fabsf(d); s_sq2 = fmaf(d, d, s_sq2);
        d = av.z - v2.z; s_abs2 += fabsf(d); s_sq2 = fmaf(d, d, s_sq2);
        d = av.w - v2.w; s_abs2 += fabsf(d); s_sq2 = fmaf(d, d, s_sq2);
    }

    // warp reduce
    #pragma unroll
    for (int off = 16; off > 0; off >>= 1) {
        s_abs1 += __shfl_down_sync(0xFFFFFFFF, s_abs1, off);
        s_abs2 += __shfl_down_sync(0xFFFFFFFF, s_abs2, off);
        s_sq1  += __shfl_down_sync(0xFFFFFFFF, s_sq1,  off);
        s_sq2  += __shfl_down_sync(0xFFFFFFFF, s_sq2,  off);
    }

    __shared__ float4 warp_sums[THREADS / 32];
    __shared__ bool is_last;
    const int wid = tid >> 5;
    const int lid = tid & 31;
    if (tid == 0) is_last = false;
    if (lid == 0) warp_sums[wid] = make_float4(s_abs1, s_abs2, s_sq1, s_sq2);
    __syncthreads();

    if (tid == 0) {
        float4 v = warp_sums[0];
        #pragma unroll
        for (int w = 1; w < THREADS / 32; w++) {
            float4 p = warp_sums[w];
            v.x += p.x; v.y += p.y; v.z += p.z; v.w += p.w;
        }
        const float l1_1 = v.x, l1_2 = v.y, sse1 = v.z, sse2 = v.w;
        const bool swap = (l1_1 >= l1_2);
        const float near_sse = swap ? sse2 : sse1;
        const float far_sse  = swap ? sse1 : sse2;
        const float la = label[b];
        const float l1 = label[i1];
        const float l2 = label[i2];
        const float near_label = swap ? l2 : l1;
        const float far_label  = swap ? l1 : l2;
        const float dfar  = la - far_label;
        const float dnear = la - near_label;
        const float alpha = dfar * dfar - dnear * dnear;
        const float loss = near_sse - far_sse + alpha * MARGIN;
        g_loss[b] = (loss > 0.0f) ? loss : 0.0f;

        __threadfence();
        const unsigned int c = atomicAdd(&g_count, 1u);
        is_last = (c == (unsigned int)(gridDim.x - 1));
        if (is_last) g_count = 0;   // reset for next replay (we are the only live CTA)
    }
    __syncthreads();

    // Last CTA: sum all 8192 per-row losses (32KB, L2-resident) into out[0].
    if (is_last) {
        // 2048 float4s over 256 threads = 8 each. __ldcg: bypass L1 (values
        // were written by other SMs).
        const float4* p = (const float4*)g_loss;
        float s = 0.f;
        #pragma unroll
        for (int k = 0; k < 8; k++) {
            float4 x = __ldcg(p + k * THREADS + tid);
            s += (x.x + x.y) + (x.z + x.w);
        }

        #pragma unroll
        for (int off = 16; off > 0; off >>= 1)
            s += __shfl_down_sync(0xFFFFFFFF, s, off);

        __shared__ float warp_sum[THREADS / 32];
        if (lid == 0) warp_sum[wid] = s;
        __syncthreads();

        if (wid == 0) {
            float t = (lid < THREADS / 32) ? warp_sum[lid] : 0.f;
            #pragma unroll
            for (int off = (THREADS / 64); off > 0; off >>= 1)
                t += __shfl_down_sync(0xFFFFFFFF, t, off);
            if (lid == 0) out[0] = t;
        }
    }
}

extern "C" void kernel_launch(void* const* d_in, const int* in_sizes, int n_in,
                              void* d_out, int out_size) {
    const float* feats = (const float*)d_in[0];
    const float* label = (const float*)d_in[1];
    const int*   idx1  = (const int*)d_in[2];
    const int*   idx2  = (const int*)d_in[3];
    float* out = (float*)d_out;

    triplet_loss_kernel<<<B_CONST, THREADS>>>(feats, label, idx1, idx2, out);
}

// round 14
// speedup vs baseline: 1.0595x; 1.0595x over previous
#include <cuda_runtime.h>

#define B_CONST 8192
#define D_CONST 4096
#define MARGIN 0.5f
#define THREADS 256

// Scalar accumulator + completion counter. Both return to 0 at the end of
// every launch (last CTA resets them), so replays are self-consistent.
__device__ float g_acc = 0.f;
__device__ unsigned int g_count = 0;

__global__ __launch_bounds__(THREADS) void triplet_loss_kernel(
    const float* __restrict__ feats,
    const float* __restrict__ label,
    const int* __restrict__ idx1,
    const int* __restrict__ idx2,
    float* __restrict__ out)
{
    const int b = blockIdx.x;
    const int tid = threadIdx.x;

    const int i1 = idx1[b];
    const int i2 = idx2[b];

    const float4* __restrict__ a  = (const float4*)(feats + (long long)b  * D_CONST);
    const float4* __restrict__ t1 = (const float4*)(feats + (long long)i1 * D_CONST);
    const float4* __restrict__ t2 = (const float4*)(feats + (long long)i2 * D_CONST);

    float s_abs1 = 0.f, s_abs2 = 0.f, s_sq1 = 0.f, s_sq2 = 0.f;

    const int NV = D_CONST / 4;  // 1024 float4s per row
    #pragma unroll
    for (int i = tid; i < NV; i += THREADS) {
        float4 av = __ldg(a + i);
        float4 v1 = __ldg(t1 + i);
        float4 v2 = __ldg(t2 + i);

        float d;
        d = av.x - v1.x; s_abs1 += fabsf(d); s_sq1 = fmaf(d, d, s_sq1);
        d = av.y - v1.y; s_abs1 += fabsf(d); s_sq1 = fmaf(d, d, s_sq1);
        d = av.z - v1.z; s_abs1 += fabsf(d); s_sq1 = fmaf(d, d, s_sq1);
        d = av.w - v1.w; s_abs1 += fabsf(d); s_sq1 = fmaf(d, d, s_sq1);

        d = av.x - v2.x; s_abs2 += fabsf(d); s_sq2 = fmaf(d, d, s_sq2);
        d = av.y - v2.y; s_abs2 += fabsf(d); s_sq2 = fmaf(d, d, s_sq2);
        d = av.z - v2.z; s_abs2 += fabsf(d); s_sq2 = fmaf(d, d, s_sq2);
        d = av.w - v2.w; s_abs2 += fabsf(d); s_sq2 = fmaf(d, d, s_sq2);
    }

    // warp reduce
    #pragma unroll
    for (int off = 16; off > 0; off >>= 1) {
        s_abs1 += __shfl_down_sync(0xFFFFFFFF, s_abs1, off);
        s_abs2 += __shfl_down_sync(0xFFFFFFFF, s_abs2, off);
        s_sq1  += __shfl_down_sync(0xFFFFFFFF, s_sq1,  off);
        s_sq2  += __shfl_down_sync(0xFFFFFFFF, s_sq2,  off);
    }

    __shared__ float4 warp_sums[THREADS / 32];
    const int wid = tid >> 5;
    const int lid = tid & 31;
    if (lid == 0) warp_sums[wid] = make_float4(s_abs1, s_abs2, s_sq1, s_sq2);
    __syncthreads();

    if (tid == 0) {
        float4 v = warp_sums[0];
        #pragma unroll
        for (int w = 1; w < THREADS / 32; w++) {
            float4 p = warp_sums[w];
            v.x += p.x; v.y += p.y; v.z += p.z; v.w += p.w;
        }
        const float l1_1 = v.x, l1_2 = v.y, sse1 = v.z, sse2 = v.w;
        const bool swap = (l1_1 >= l1_2);
        const float near_sse = swap ? sse2 : sse1;
        const float far_sse  = swap ? sse1 : sse2;
        const float la = label[b];
        const float l1 = label[i1];
        const float l2 = label[i2];
        const float near_label = swap ? l2 : l1;
        const float far_label  = swap ? l1 : l2;
        const float dfar  = la - far_label;
        const float dnear = la - near_label;
        const float alpha = dfar * dfar - dnear * dnear;
        float loss = near_sse - far_sse + alpha * MARGIN;
        loss = (loss > 0.0f) ? loss : 0.0f;

        // Accumulate into the global scalar (relaxed reduction, no return).
        asm volatile("red.relaxed.gpu.global.add.f32 [%0], %1;"
                     :: "l"(&g_acc), "f"(loss) : "memory");

        // acq_rel counter: release orders our red.add before the increment;
        // acquire (when we read 8191) makes all other CTAs' adds visible.
        // Native STRONG.GPU atomic — no membar, no CCTL.IVALL L1 flush.
        unsigned int c;
        asm volatile("atom.acq_rel.gpu.global.add.u32 %0, [%1], 1;"
                     : "=r"(c) : "l"(&g_count) : "memory");

        if (c == (unsigned int)(B_CONST - 1)) {
            float total;
            asm volatile("ld.acquire.gpu.global.f32 %0, [%1];"
                         : "=f"(total) : "l"(&g_acc) : "memory");
            out[0] = total;
            // Reset for the next replay; kernel-completion ordering makes
            // these visible before any CTA of the next launch runs.
            g_acc = 0.f;
            g_count = 0;
        }
    }
}

extern "C" void kernel_launch(void* const* d_in, const int* in_sizes, int n_in,
                              void* d_out, int out_size) {
    const float* feats = (const float*)d_in[0];
    const float* label = (const float*)d_in[1];
    const int*   idx1  = (const int*)d_in[2];
    const int*   idx2  = (const int*)d_in[3];
    float* out = (float*)d_out;

    triplet_loss_kernel<<<B_CONST, THREADS>>>(feats, label, idx1, idx2, out);
}

// round 15
// speedup vs baseline: 1.1127x; 1.0502x over previous
#include <cuda_runtime.h>

#define B_CONST 8192
#define D_CONST 4096
#define MARGIN 0.5f
#define THREADS 256
#define NSLOTS 64
#define SLOT_STRIDE 32   // floats: 128B padding between slots

// Partial-sum slots; zero-initialized at module load, reset by the tail kernel
// after every replay. 64 slots * 128B apart -> spread across L2 slices.
__device__ float g_slots[NSLOTS * SLOT_STRIDE];

__global__ __launch_bounds__(THREADS) void triplet_loss_kernel(
    const float* __restrict__ feats,
    const float* __restrict__ label,
    const int* __restrict__ idx1,
    const int* __restrict__ idx2)
{
    const int b = blockIdx.x;
    const int tid = threadIdx.x;

    const int i1 = idx1[b];
    const int i2 = idx2[b];

    const float4* __restrict__ a  = (const float4*)(feats + (long long)b  * D_CONST);
    const float4* __restrict__ t1 = (const float4*)(feats + (long long)i1 * D_CONST);
    const float4* __restrict__ t2 = (const float4*)(feats + (long long)i2 * D_CONST);

    float s_abs1 = 0.f, s_abs2 = 0.f, s_sq1 = 0.f, s_sq2 = 0.f;

    const int NV = D_CONST / 4;  // 1024 float4s per row
    #pragma unroll
    for (int i = tid; i < NV; i += THREADS) {
        float4 av = __ldg(a + i);
        float4 v1 = __ldg(t1 + i);
        float4 v2 = __ldg(t2 + i);

        float d;
        d = av.x - v1.x; s_abs1 += fabsf(d); s_sq1 = fmaf(d, d, s_sq1);
        d = av.y - v1.y; s_abs1 += fabsf(d); s_sq1 = fmaf(d, d, s_sq1);
        d = av.z - v1.z; s_abs1 += fabsf(d); s_sq1 = fmaf(d, d, s_sq1);
        d = av.w - v1.w; s_abs1 += fabsf(d); s_sq1 = fmaf(d, d, s_sq1);

        d = av.x - v2.x; s_abs2 += fabsf(d); s_sq2 = fmaf(d, d, s_sq2);
        d = av.y - v2.y; s_abs2 += fabsf(d); s_sq2 = fmaf(d, d, s_sq2);
        d = av.z - v2.z; s_abs2 += fabsf(d); s_sq2 = fmaf(d, d, s_sq2);
        d = av.w - v2.w; s_abs2 += fabsf(d); s_sq2 = fmaf(d, d, s_sq2);
    }

    // warp reduce
    #pragma unroll
    for (int off = 16; off > 0; off >>= 1) {
        s_abs1 += __shfl_down_sync(0xFFFFFFFF, s_abs1, off);
        s_abs2 += __shfl_down_sync(0xFFFFFFFF, s_abs2, off);
        s_sq1  += __shfl_down_sync(0xFFFFFFFF, s_sq1,  off);
        s_sq2  += __shfl_down_sync(0xFFFFFFFF, s_sq2,  off);
    }

    __shared__ float4 warp_sums[THREADS / 32];
    const int wid = tid >> 5;
    const int lid = tid & 31;
    if (lid == 0) warp_sums[wid] = make_float4(s_abs1, s_abs2, s_sq1, s_sq2);
    __syncthreads();

    if (tid == 0) {
        float4 v = warp_sums[0];
        #pragma unroll
        for (int w = 1; w < THREADS / 32; w++) {
            float4 p = warp_sums[w];
            v.x += p.x; v.y += p.y; v.z += p.z; v.w += p.w;
        }
        const float l1_1 = v.x, l1_2 = v.y, sse1 = v.z, sse2 = v.w;
        const bool swap = (l1_1 >= l1_2);
        const float near_sse = swap ? sse2 : sse1;
        const float far_sse  = swap ? sse1 : sse2;
        const float la = label[b];
        const float l1 = label[i1];
        const float l2 = label[i2];
        const float near_label = swap ? l2 : l1;
        const float far_label  = swap ? l1 : l2;
        const float dfar  = la - far_label;
        const float dnear = la - near_label;
        const float alpha = dfar * dfar - dnear * dnear;
        float loss = near_sse - far_sse + alpha * MARGIN;
        loss = (loss > 0.0f) ? loss : 0.0f;

        // Fire-and-forget scattered reduction (REDG, no return, no ordering):
        // CTA retires without waiting for the L2 round trip.
        asm volatile("red.relaxed.gpu.global.add.f32 [%0], %1;"
                     :: "l"(&g_slots[(b & (NSLOTS - 1)) * SLOT_STRIDE]),
                        "f"(loss) : "memory");
    }
}

// Tail: launched with PDL; parks at griddepcontrol.wait until the primary
// grid completes (implicit trigger = full memory visibility), then sums the
// 64 slots, writes out[0], and resets the slots for the next replay.
__global__ __launch_bounds__(NSLOTS) void tail_reduce_kernel(float* __restrict__ out) {
    asm volatile("griddepcontrol.wait;" ::: "memory");

    const int tid = threadIdx.x;
    float s = g_slots[tid * SLOT_STRIDE];
    g_slots[tid * SLOT_STRIDE] = 0.f;   // reset for next replay

    // reduce 64 values: 2 warps
    #pragma unroll
    for (int off = 16; off > 0; off >>= 1)
        s += __shfl_down_sync(0xFFFFFFFF, s, off);

    __shared__ float wsum[2];
    if ((tid & 31) == 0) wsum[tid >> 5] = s;
    __syncthreads();
    if (tid == 0) out[0] = wsum[0] + wsum[1];
}

extern "C" void kernel_launch(void* const* d_in, const int* in_sizes, int n_in,
                              void* d_out, int out_size) {
    const float* feats = (const float*)d_in[0];
    const float* label = (const float*)d_in[1];
    const int*   idx1  = (const int*)d_in[2];
    const int*   idx2  = (const int*)d_in[3];
    float* out = (float*)d_out;

    triplet_loss_kernel<<<B_CONST, THREADS>>>(feats, label, idx1, idx2);

    // Tail with programmatic dependent launch: overlaps its launch latency
    // with the primary's execution.
    cudaLaunchConfig_t cfg = {};
    cfg.gridDim = dim3(1, 1, 1);
    cfg.blockDim = dim3(NSLOTS, 1, 1);
    cfg.dynamicSmemBytes = 0;
    cfg.stream = 0;
    cudaLaunchAttribute attr[1];
    attr[0].id = cudaLaunchAttributeProgrammaticStreamSerialization;
    attr[0].val.programmaticStreamSerializationAllowed = 1;
    cfg.attrs = attr;
    cfg.numAttrs = 1;

    cudaError_t e = cudaLaunchKernelEx(&cfg, tail_reduce_kernel, out);
    if (e != cudaSuccess) {
        // PDL rejected (e.g. unsupported in this capture mode): plain launch.
        tail_reduce_kernel<<<1, NSLOTS>>>(out);
    }
}